// round 2
// baseline (speedup 1.0000x reference)
#include <cuda_runtime.h>
#include <cuda_bf16.h>

// BuildCost: light-field disparity cost volume.
// x:   (b=2, c=16, n=25, h=128, w=128) fp32, n = a1*5 + a2 (A=5)
// out: (b, c, n, D=9, h, w) fp32
// out[bc, n, di, h, w] = x[bc, n, h + d*(2-a1), w + d*(2-a2)],  d = di - 4,
// zero when the shifted row/col falls outside [0,128).
//
// Memory-bound: 472 MB written, ~52 MB read (input fits L2; each row reused
// across 9 disparities). One thread per float4 of output -> coalesced STG.128.

#define AR    5
#define DD    9
#define MIND  (-4)
#define HH    128
#define WW    128
#define PLANE (HH * WW)          // 16384 floats per (bc,n) plane
#define WVEC  (WW / 4)           // 32 float4 per row

__global__ __launch_bounds__(256)
void build_cost_kernel(const float* __restrict__ x,
                       float* __restrict__ out,
                       int total_vec) {
    int i = blockIdx.x * blockDim.x + threadIdx.x;
    if (i >= total_vec) return;

    // decompose: i = ((((bc*25 + n)*9 + di)*128 + h)*32 + wv)
    int wv = i & (WVEC - 1);
    int t  = i >> 5;
    int h  = t & (HH - 1);
    t >>= 7;
    int di = t % DD;
    t /= DD;
    int n  = t % (AR * AR);
    int bc = t / (AR * AR);

    int a1 = n / AR;
    int a2 = n - a1 * AR;
    int d  = di + MIND;

    int sh = h + d * (2 - a1);

    float4 v = make_float4(0.f, 0.f, 0.f, 0.f);
    if ((unsigned)sh < (unsigned)HH) {
        const float* __restrict__ src =
            x + ((long)(bc * (AR * AR) + n)) * PLANE + sh * WW;
        int sw = (wv << 2) + d * (2 - a2);   // shifted source column of lane 0

        if (sw >= 0 && sw + 3 < WW) {
            // fully in-bounds (common case): 4 scalar loads, L1/L2 hits
            v.x = src[sw];
            v.y = src[sw + 1];
            v.z = src[sw + 2];
            v.w = src[sw + 3];
        } else {
            if ((unsigned)(sw    ) < (unsigned)WW) v.x = src[sw    ];
            if ((unsigned)(sw + 1) < (unsigned)WW) v.y = src[sw + 1];
            if ((unsigned)(sw + 2) < (unsigned)WW) v.z = src[sw + 2];
            if ((unsigned)(sw + 3) < (unsigned)WW) v.w = src[sw + 3];
        }
    }

    reinterpret_cast<float4*>(out)[i] = v;
}

extern "C" void kernel_launch(void* const* d_in, const int* in_sizes, int n_in,
                              void* d_out, int out_size) {
    const float* x = (const float*)d_in[0];
    float* out = (float*)d_out;

    // out_size = 2*16*25*9*128*128 = 117,964,800 floats -> 29,491,200 float4
    int total_vec = out_size / 4;
    int threads = 256;
    int blocks = (total_vec + threads - 1) / threads;

    build_cost_kernel<<<blocks, threads>>>(x, out, total_vec);
}

// round 3
// speedup vs baseline: 1.3731x; 1.3731x over previous
#include <cuda_runtime.h>
#include <cuda_bf16.h>

// BuildCost: light-field disparity cost volume (smem-tiled, halo-padded).
// x:   (bc=32, n=25, h=128, w=128) fp32, n = a1*5 + a2 (A=5)
// out: (bc, n, D=9, h, w) fp32
// out[bc,n,di,h,w] = x[bc,n, h + d*(2-a1), w + d*(2-a2)], d = di-4, 0 if OOB.
//
// Each block stages one (bc,n) 32-row tile (+8-row/col zero halo) into smem,
// then emits all 9 disparity-shifted copies. Input is read from global ONCE
// per block (was 9x), so L1 load wavefronts drop ~9x -> DRAM-write bound.

#define AR     5
#define DD     9
#define HH     128
#define WW     128
#define PLANE  (HH * WW)
#define HTILE  32
#define HALO   8
#define SROWS  (HTILE + 2 * HALO)   // 48
#define SWID   (WW + 2 * HALO)      // 144 floats per smem row

__global__ __launch_bounds__(256)
void build_cost_kernel(const float* __restrict__ x,
                       float* __restrict__ out) {
    __shared__ float s[SROWS * SWID];   // 27,648 B

    const int tid = threadIdx.x;
    const int n   = blockIdx.y;          // 0..24
    const int bc  = blockIdx.z;          // 0..31
    const int h0  = blockIdx.x * HTILE;  // 0,32,64,96
    const int a1  = n / AR;
    const int a2  = n - a1 * AR;

    // ---- stage 1: zero the padded tile (halo + OOB rows) ----
    float4* s4 = reinterpret_cast<float4*>(s);
    #pragma unroll
    for (int j = tid; j < (SROWS * SWID) / 4; j += 256)
        s4[j] = make_float4(0.f, 0.f, 0.f, 0.f);
    __syncthreads();

    // ---- stage 2: load valid input rows (float4, coalesced) ----
    const float* __restrict__ plane = x + (bc * (AR * AR) + n) * PLANE;
    #pragma unroll
    for (int j = tid; j < SROWS * (WW / 4); j += 256) {
        int r  = j >> 5;          // smem row 0..47
        int cv = j & 31;          // float4 within row
        int gr = h0 - HALO + r;   // global input row
        if ((unsigned)gr < (unsigned)HH) {
            float4 v = reinterpret_cast<const float4*>(plane + gr * WW)[cv];
            // dst offset 8 floats = 32 B -> 16B-aligned, st.shared.v4 OK
            *reinterpret_cast<float4*>(&s[r * SWID + HALO + cv * 4]) = v;
        }
    }
    __syncthreads();

    // ---- stage 3: emit 9 disparities x 32 rows, branch-free gathers ----
    const int warp = tid >> 5;
    const int lane = tid & 31;
    const int outBase = (bc * (AR * AR) + n) * (DD * PLANE) + h0 * WW;

    // 288 (di,row) pairs, 8 warps -> 36 per warp
    for (int p = warp; p < DD * HTILE; p += 8) {
        int di = p >> 5;                 // p / 32
        int hr = p & 31;                 // p % 32
        int d  = di - 4;
        // padded smem coords: always in-bounds thanks to halo
        const float* __restrict__ srow =
            &s[(hr + HALO + d * (2 - a1)) * SWID + HALO + d * (2 - a2)];
        float* __restrict__ orow = out + outBase + di * PLANE + hr * WW;

        float v0 = srow[lane];
        float v1 = srow[lane + 32];
        float v2 = srow[lane + 64];
        float v3 = srow[lane + 96];
        orow[lane]      = v0;
        orow[lane + 32] = v1;
        orow[lane + 64] = v2;
        orow[lane + 96] = v3;
    }
}

extern "C" void kernel_launch(void* const* d_in, const int* in_sizes, int n_in,
                              void* d_out, int out_size) {
    const float* x = (const float*)d_in[0];
    float* out = (float*)d_out;

    dim3 grid(HH / HTILE, AR * AR, 32);   // 4 x 25 x 32 = 3200 blocks
    build_cost_kernel<<<grid, 256>>>(x, out);
}

// round 4
// speedup vs baseline: 1.3999x; 1.0195x over previous
#include <cuda_runtime.h>
#include <cuda_bf16.h>

// BuildCost: light-field disparity cost volume (smem-tiled, vectorized emit).
// x:   (bc=32, n=25, h=128, w=128) fp32, n = a1*5 + a2 (A=5)
// out: (bc, n, D=9, h, w) fp32
// out[bc,n,di,h,w] = x[bc,n, h+d*(2-a1), w+d*(2-a2)], d = di-4, 0 if OOB.
//
// Column shift is warp-uniform per (di,row): gather via two aligned
// conflict-free LDS.128 + uniform select, emit one STG.128 (512B/12cyc
// vs 4x STG.32 at 512B/20cyc -> lifts LSU store-issue cap).

#define AR     5
#define DD     9
#define HH     128
#define WW     128
#define PLANE  (HH * WW)
#define HTILE  32
#define HALO   8
#define SROWS  (HTILE + 2 * HALO)   // 48
#define SWID   148                  // 8 + 128 + 8 + 4 spare (row stride 592B, 16B-aligned)

__global__ __launch_bounds__(256)
void build_cost_kernel(const float* __restrict__ x,
                       float* __restrict__ out) {
    __shared__ float s[SROWS * SWID];   // 28,416 B

    const int tid = threadIdx.x;
    const int n   = blockIdx.y;          // 0..24
    const int bc  = blockIdx.z;          // 0..31
    const int h0  = blockIdx.x * HTILE;  // 0,32,64,96
    const int a1  = n / AR;
    const int a2  = n - a1 * AR;

    // ---- stage 1: zero the padded tile (halo + OOB rows) ----
    float4* s4 = reinterpret_cast<float4*>(s);
    #pragma unroll
    for (int j = tid; j < (SROWS * SWID) / 4; j += 256)
        s4[j] = make_float4(0.f, 0.f, 0.f, 0.f);
    __syncthreads();

    // ---- stage 2: load valid input rows (float4, coalesced) ----
    const float* __restrict__ plane = x + (bc * (AR * AR) + n) * PLANE;
    #pragma unroll
    for (int j = tid; j < SROWS * (WW / 4); j += 256) {
        int r  = j >> 5;          // smem row 0..47
        int cv = j & 31;          // float4 within row
        int gr = h0 - HALO + r;   // global input row
        if ((unsigned)gr < (unsigned)HH) {
            float4 v = reinterpret_cast<const float4*>(plane + gr * WW)[cv];
            *reinterpret_cast<float4*>(&s[r * SWID + HALO + cv * 4]) = v;
        }
    }
    __syncthreads();

    // ---- stage 3: 9 disparities x 32 rows, vectorized shifted copy ----
    const int warp = tid >> 5;
    const int lane = tid & 31;
    float* __restrict__ outP =
        out + (size_t)(bc * (AR * AR) + n) * (DD * PLANE) + h0 * WW;

    #pragma unroll
    for (int di = 0; di < DD; ++di) {
        const int d  = di - 4;
        const int sc = d * (2 - a2);    // warp-uniform column shift, -8..8
        const int q  = sc >> 2;         // arithmetic shift = floor
        const int rm = sc & 3;
        const int rowShift = HALO + d * (2 - a1);
        float* __restrict__ oplane = outP + di * PLANE;

        #pragma unroll
        for (int k = 0; k < 4; ++k) {
            const int hr = warp + 8 * k;           // 8 warps x 4 = 32 rows
            // row base: (hr+rowShift)*592B, 16B-aligned
            const float4* __restrict__ s4row =
                reinterpret_cast<const float4*>(&s[(hr + rowShift) * SWID]) + (HALO / 4);

            float4 A = s4row[lane + q];
            float4 B = s4row[lane + q + 1];
            float4 v;
            if      (rm == 0) v = A;
            else if (rm == 1) v = make_float4(A.y, A.z, A.w, B.x);
            else if (rm == 2) v = make_float4(A.z, A.w, B.x, B.y);
            else              v = make_float4(A.w, B.x, B.y, B.z);

            reinterpret_cast<float4*>(oplane + hr * WW)[lane] = v;
        }
    }
}

extern "C" void kernel_launch(void* const* d_in, const int* in_sizes, int n_in,
                              void* d_out, int out_size) {
    const float* x = (const float*)d_in[0];
    float* out = (float*)d_out;

    dim3 grid(HH / HTILE, AR * AR, 32);   // 4 x 25 x 32 = 3200 blocks
    build_cost_kernel<<<grid, 256>>>(x, out);
}

// round 5
// speedup vs baseline: 1.4070x; 1.0051x over previous
#include <cuda_runtime.h>
#include <cuda_bf16.h>

// BuildCost: light-field disparity cost volume.
// x:   (bc=32, n=25, h=128, w=128) fp32, n = a1*5 + a2 (A=5)
// out: (bc, n, D=9, h, w) fp32
// out[bc,n,di,h,w] = x[bc,n, h+d*(2-a1), w+d*(2-a2)], d = di-4, 0 if OOB.
//
// R5: single-pass staging (each smem slot written once: zero OR global),
// one barrier instead of two; streaming stores (__stcs) so the 472MB write
// stream doesn't churn L2.

#define AR     5
#define DD     9
#define HH     128
#define WW     128
#define PLANE  (HH * WW)
#define HTILE  32
#define HALO   8
#define SROWS  (HTILE + 2 * HALO)   // 48
#define SWID   148                  // 8 halo + 128 + 8 halo + 4 spare; 592B stride, 16B-aligned
#define SVEC   (SWID / 4)           // 37 float4 per smem row

__global__ __launch_bounds__(256)
void build_cost_kernel(const float* __restrict__ x,
                       float* __restrict__ out) {
    __shared__ float s[SROWS * SWID];   // 28,416 B

    const int tid = threadIdx.x;
    const int n   = blockIdx.y;          // 0..24
    const int bc  = blockIdx.z;          // 0..31
    const int h0  = blockIdx.x * HTILE;  // 0,32,64,96
    const int a1  = n / AR;
    const int a2  = n - a1 * AR;

    // ---- stage 1 (fused): fill padded tile in ONE pass ----
    // smem float4 slot j: row r = j/37, vec cv = j%37.
    // global cols gc0 = cv*4 - 8; interior iff 2 <= cv <= 33 (gc0 in [0,124]).
    const float* __restrict__ plane = x + (bc * (AR * AR) + n) * PLANE;
    #pragma unroll 2
    for (int j = tid; j < SROWS * SVEC; j += 256) {
        int r  = j / SVEC;
        int cv = j - r * SVEC;
        int gr = h0 - HALO + r;
        float4 v = make_float4(0.f, 0.f, 0.f, 0.f);
        if ((unsigned)gr < (unsigned)HH && (unsigned)(cv - 2) < 32u)
            v = reinterpret_cast<const float4*>(plane + gr * WW)[cv - 2];
        *reinterpret_cast<float4*>(&s[r * SWID + cv * 4]) = v;
    }
    __syncthreads();

    // ---- stage 2: 9 disparities x 32 rows, vectorized shifted copy ----
    const int warp = tid >> 5;
    const int lane = tid & 31;
    float* __restrict__ outP =
        out + (size_t)(bc * (AR * AR) + n) * (DD * PLANE) + h0 * WW;

    #pragma unroll
    for (int di = 0; di < DD; ++di) {
        const int d  = di - 4;
        const int sc = d * (2 - a2);    // warp-uniform column shift, -8..8
        const int q  = sc >> 2;         // floor div 4
        const int rm = sc & 3;
        const int rowShift = HALO + d * (2 - a1);
        float* __restrict__ oplane = outP + di * PLANE;

        #pragma unroll
        for (int k = 0; k < 4; ++k) {
            const int hr = warp + 8 * k;           // 8 warps x 4 = 32 rows
            const float4* __restrict__ s4row =
                reinterpret_cast<const float4*>(&s[(hr + rowShift) * SWID]) + (HALO / 4);

            float4 A = s4row[lane + q];
            float4 B = s4row[lane + q + 1];
            float4 v;
            if      (rm == 0) v = A;
            else if (rm == 1) v = make_float4(A.y, A.z, A.w, B.x);
            else if (rm == 2) v = make_float4(A.z, A.w, B.x, B.y);
            else              v = make_float4(A.w, B.x, B.y, B.z);

            __stcs(reinterpret_cast<float4*>(oplane + hr * WW) + lane, v);
        }
    }
}

extern "C" void kernel_launch(void* const* d_in, const int* in_sizes, int n_in,
                              void* d_out, int out_size) {
    const float* x = (const float*)d_in[0];
    float* out = (float*)d_out;

    dim3 grid(HH / HTILE, AR * AR, 32);   // 4 x 25 x 32 = 3200 blocks
    build_cost_kernel<<<grid, 256>>>(x, out);
}